// round 9
// baseline (speedup 1.0000x reference)
#include <cuda_runtime.h>
#include <math.h>
#include <stdint.h>

#define Gn 8
#define Hn 64
#define In 64
#define Bn 32
#define Tn 1000
#define XSTR (Gn * In)   // 512 floats per (b,t)

// ---------------- packed f32x2 helpers (sm_103a) ----------------
__device__ __forceinline__ uint64_t ffma2(uint64_t a, uint64_t b, uint64_t c) {
    uint64_t d;
    asm("fma.rn.f32x2 %0, %1, %2, %3;" : "=l"(d) : "l"(a), "l"(b), "l"(c));
    return d;
}
__device__ __forceinline__ uint64_t fadd2(uint64_t a, uint64_t b) {
    uint64_t d;
    asm("add.rn.f32x2 %0, %1, %2;" : "=l"(d) : "l"(a), "l"(b));
    return d;
}
__device__ __forceinline__ uint64_t pack2(float lo, float hi) {
    uint64_t d;
    asm("mov.b64 %0, {%1, %2};" : "=l"(d) : "f"(lo), "f"(hi));
    return d;
}
__device__ __forceinline__ float2 unpack2(uint64_t v) {
    float lo, hi;
    asm("mov.b64 {%0, %1}, %2;" : "=f"(lo), "=f"(hi) : "l"(v));
    return make_float2(lo, hi);
}
__device__ __forceinline__ float fsig(float x) {
    return __fdividef(1.f, 1.f + __expf(-x));
}

// Two 64-wide dots sharing the same vector v (loaded ONCE: 16 LDS.128).
// wA, wB: 16 ulonglong2 each (64 floats). Seeds folded into chain 0.
__device__ __forceinline__ float2 dot64x2(const ulonglong2* wA, const ulonglong2* wB,
                                          const float* v, float seedA, float seedB) {
    const ulonglong2* v2 = (const ulonglong2*)v;
    uint64_t a0 = pack2(seedA, 0.f), a1 = 0ull, a2 = 0ull, a3 = 0ull;
    uint64_t b0 = pack2(seedB, 0.f), b1 = 0ull, b2 = 0ull, b3 = 0ull;
#pragma unroll
    for (int q = 0; q < 16; q += 2) {
        ulonglong2 va = v2[q];
        ulonglong2 vb = v2[q + 1];
        a0 = ffma2(wA[q].x,     va.x, a0);
        a1 = ffma2(wA[q].y,     va.y, a1);
        a2 = ffma2(wA[q + 1].x, vb.x, a2);
        a3 = ffma2(wA[q + 1].y, vb.y, a3);
        b0 = ffma2(wB[q].x,     va.x, b0);
        b1 = ffma2(wB[q].y,     va.y, b1);
        b2 = ffma2(wB[q + 1].x, vb.x, b2);
        b3 = ffma2(wB[q + 1].y, vb.y, b3);
    }
    float2 fa = unpack2(fadd2(fadd2(a0, a1), fadd2(a2, a3)));
    float2 fb = unpack2(fadd2(fadd2(b0, b1), fadd2(b2, b3)));
    return make_float2(fa.x + fa.y, fb.x + fb.y);
}

// ---------------------------------------------------------------------------
// Fused GRU, vector-split roles. One block per (b,g); 192 threads.
//  H-threads j in [0,96):  own Whh rows (j, j+96); load h_sh once/step.
//  X-threads j in [96,192): own Wih rows (i, i+96), i=j-96; load x_sh once.
//  Gates: j<64. Loaders: j in [64,80) stream x via a 4-slot smem ring.
// grid = 256, block = 192, 2 blocks/SM (single wave)
// ---------------------------------------------------------------------------
__global__ void __launch_bounds__(192, 2) gru_fused_kernel(
    const float* __restrict__ x,
    const float* __restrict__ h0,
    const float* __restrict__ Wih,
    const float* __restrict__ Whh,
    const float* __restrict__ bih,
    const float* __restrict__ bhh,
    float* __restrict__ out)
{
    const int b = blockIdx.x >> 3;
    const int g = blockIdx.x & 7;
    const int j = threadIdx.x;

    __shared__ __align__(16) float h_sh[64];
    __shared__ __align__(16) float gh_sh[192];
    __shared__ __align__(16) float xq_sh[4][192];
    __shared__ __align__(16) float x_sh[4][64];

    const bool isH = (j < 96);
    const int  i   = isH ? j : (j - 96);

    // Two weight rows (i and i+96) of Whh (H-threads) or Wih (X-threads)
    ulonglong2 wA[16], wB[16];
    {
        const float* Wsrc = isH ? Whh : Wih;
        const ulonglong2* pA = (const ulonglong2*)&Wsrc[((size_t)g * 192 + i) * 64];
        const ulonglong2* pB = (const ulonglong2*)&Wsrc[((size_t)g * 192 + i + 96) * 64];
#pragma unroll
        for (int q = 0; q < 16; q++) { wA[q] = pA[q]; wB[q] = pB[q]; }
    }
    const float* bsrc = isH ? bhh : bih;
    const float seedA = bsrc[g * 192 + i];
    const float seedB = bsrc[g * 192 + i + 96];

    const float* xsrc = x + ((size_t)b * Tn) * XSTR + g * In;

    const int  lj     = j - 64;
    const bool loader = ((unsigned)lj < 16u);   // threads 64..79 (H side)
    const bool gate   = (j < 64);

    // ---- prolog ----
    float hreg = 0.f;
    if (gate) {
        hreg = h0[((size_t)g * Bn + b) * Hn + j];
        h_sh[j] = hreg;
#pragma unroll
        for (int s = 0; s < 4; s++) x_sh[s][j] = xsrc[(size_t)s * XSTR + j];
    }
    __syncthreads();

    // X-threads fill xq slots 0,1 (steps 0 and 1); loaders stage x(4), x(5)
    if (!isH) {
        float2 d0 = dot64x2(wA, wB, x_sh[0], seedA, seedB);
        xq_sh[0][i] = d0.x;  xq_sh[0][i + 96] = d0.y;
        float2 d1 = dot64x2(wA, wB, x_sh[1], seedA, seedB);
        xq_sh[1][i] = d1.x;  xq_sh[1][i + 96] = d1.y;
    }
    float4 xa4 = make_float4(0.f, 0.f, 0.f, 0.f);
    float4 xb4 = xa4;
    if (loader) {
        xa4 = *(const float4*)&xsrc[(size_t)4 * XSTR + lj * 4];
        xb4 = *(const float4*)&xsrc[(size_t)5 * XSTR + lj * 4];
    }
    float* outp = out + (size_t)b * Tn * (Gn * Hn) + g * Hn + j;  // gates only
    __syncthreads();

#define STEP(T_, XREG_)                                                       \
    {                                                                         \
        /* phase A: H-threads do the critical recurrent dots; X-threads  */   \
        /* project x(t+2); loaders refill the x ring.                    */   \
        if (isH) {                                                            \
            float2 d = dot64x2(wA, wB, h_sh, seedA, seedB);                   \
            gh_sh[i]      = d.x;                                              \
            gh_sh[i + 96] = d.y;                                              \
            if (loader) {                                                     \
                *(float4*)&x_sh[((T_) + 4) & 3][lj * 4] = XREG_;              \
            }                                                                 \
        } else if ((T_) + 2 < Tn) {                                           \
            int sl = ((T_) + 2) & 3;                                          \
            float2 d = dot64x2(wA, wB, x_sh[sl], seedA, seedB);               \
            xq_sh[sl][i]      = d.x;                                          \
            xq_sh[sl][i + 96] = d.y;                                          \
        }                                                                     \
        __syncthreads();                                                      \
        /* phase B: gates + output; loaders fetch x(t+6) */                   \
        if (gate) {                                                           \
            const float* xq = xq_sh[(T_) & 3];                                \
            float rr = fsig(xq[j]      + gh_sh[j]);                           \
            float zz = fsig(xq[64 + j] + gh_sh[64 + j]);                      \
            float aa = xq[128 + j] + rr * gh_sh[128 + j];                     \
            float nn = __fmaf_rn(2.f, fsig(2.f * aa), -1.f);                  \
            float hn = nn + zz * (hreg - nn);                                 \
            hreg = hn;                                                        \
            h_sh[j] = hn;                                                     \
            __stcs(&outp[(size_t)(T_) * (Gn * Hn)], hn);                      \
        }                                                                     \
        if (loader) {                                                         \
            size_t tl = (size_t)min((T_) + 6, Tn - 1);                        \
            XREG_ = *(const float4*)&xsrc[tl * XSTR + lj * 4];                \
        }                                                                     \
        __syncthreads();                                                      \
    }

    for (int t = 0; t < Tn; t += 2) {
        STEP(t, xa4);
        STEP(t + 1, xb4);
    }
#undef STEP

    if (gate) {
        out[(size_t)Bn * Tn * (Gn * Hn) + ((size_t)g * Bn + b) * Hn + j] = hreg;
    }
}

// ---------------------------------------------------------------------------
extern "C" void kernel_launch(void* const* d_in, const int* in_sizes, int n_in,
                              void* d_out, int out_size)
{
    const float* x   = (const float*)d_in[0];
    const float* h0  = (const float*)d_in[1];
    const float* Wih = (const float*)d_in[2];
    const float* Whh = (const float*)d_in[3];
    const float* bih = (const float*)d_in[4];
    const float* bhh = (const float*)d_in[5];
    float* out = (float*)d_out;

    gru_fused_kernel<<<Bn * Gn, 192>>>(x, h0, Wih, Whh, bih, bhh, out);
}

// round 10
// speedup vs baseline: 1.0239x; 1.0239x over previous
#include <cuda_runtime.h>
#include <math.h>
#include <stdint.h>

#define Gn 8
#define Hn 64
#define In 64
#define Bn 32
#define Tn 1000
#define XSTR (Gn * In)   // 512 floats per (b,t)

// ---------------- packed f32x2 helpers (sm_103a) ----------------
__device__ __forceinline__ uint64_t ffma2(uint64_t a, uint64_t b, uint64_t c) {
    uint64_t d;
    asm("fma.rn.f32x2 %0, %1, %2, %3;" : "=l"(d) : "l"(a), "l"(b), "l"(c));
    return d;
}
__device__ __forceinline__ uint64_t fadd2(uint64_t a, uint64_t b) {
    uint64_t d;
    asm("add.rn.f32x2 %0, %1, %2;" : "=l"(d) : "l"(a), "l"(b));
    return d;
}
__device__ __forceinline__ uint64_t pack2(float lo, float hi) {
    uint64_t d;
    asm("mov.b64 %0, {%1, %2};" : "=l"(d) : "f"(lo), "f"(hi));
    return d;
}
__device__ __forceinline__ float2 unpack2(uint64_t v) {
    float lo, hi;
    asm("mov.b64 {%0, %1}, %2;" : "=f"(lo), "=f"(hi) : "l"(v));
    return make_float2(lo, hi);
}
__device__ __forceinline__ float fsig(float x) {
    return __fdividef(1.f, 1.f + __expf(-x));
}

// 64-wide dot: w = 16 ulonglong2 (64 floats), v = 64 floats in smem,
// seeded in chain 0's low half.
__device__ __forceinline__ float dot64(const ulonglong2* w, const float* v, float seed) {
    const ulonglong2* v2 = (const ulonglong2*)v;
    uint64_t a0 = pack2(seed, 0.f), a1 = 0ull, a2 = 0ull, a3 = 0ull;
#pragma unroll
    for (int q = 0; q < 16; q += 2) {
        ulonglong2 va = v2[q];
        ulonglong2 vb = v2[q + 1];
        a0 = ffma2(w[q].x,     va.x, a0);
        a1 = ffma2(w[q].y,     va.y, a1);
        a2 = ffma2(w[q + 1].x, vb.x, a2);
        a3 = ffma2(w[q + 1].y, vb.y, a3);
    }
    float2 f = unpack2(fadd2(fadd2(a0, a1), fadd2(a2, a3)));
    return f.x + f.y;
}

// ---------------------------------------------------------------------------
// Fused GRU (R8 skeleton, xp dot moved to phase B). One block per (b,g);
// 192 threads; thread j owns Whh row j AND Wih row j.
// Phase A (critical): gh = Whh·h only. Phase B: gates (j<64) + xp(t+2) dot
// (all threads, fills gate MUFU bubbles) + x streaming.
// grid = 256, block = 192, 2 blocks/SM (single wave)
// ---------------------------------------------------------------------------
__global__ void __launch_bounds__(192, 2) gru_fused_kernel(
    const float* __restrict__ x,
    const float* __restrict__ h0,
    const float* __restrict__ Wih,
    const float* __restrict__ Whh,
    const float* __restrict__ bih,
    const float* __restrict__ bhh,
    float* __restrict__ out)
{
    const int b = blockIdx.x >> 3;
    const int g = blockIdx.x & 7;
    const int j = threadIdx.x;

    __shared__ __align__(16) float h_sh[64];
    __shared__ __align__(16) float gh_sh[192];
    __shared__ __align__(16) float xq_sh[4][192];
    __shared__ __align__(16) float x_sh[4][64];

    // Both weight rows in registers
    ulonglong2 whh_[16], wih_[16];
    {
        const ulonglong2* p = (const ulonglong2*)&Whh[((size_t)g * 192 + j) * Hn];
#pragma unroll
        for (int q = 0; q < 16; q++) whh_[q] = p[q];
        p = (const ulonglong2*)&Wih[((size_t)g * 192 + j) * In];
#pragma unroll
        for (int q = 0; q < 16; q++) wih_[q] = p[q];
    }
    const float bhj = bhh[g * 192 + j];
    const float bij = bih[g * 192 + j];

    const float* xsrc = x + ((size_t)b * Tn) * XSTR + g * In;

    const int  lj     = j - 128;
    const bool loader = ((unsigned)lj < 16u);
    const bool gate   = (j < 64);

    // ---- prolog: fill x_sh[0..3] = x(0..3), init h ----
    float hreg = 0.f;
    if (gate) {
        hreg = h0[((size_t)g * Bn + b) * Hn + j];
        h_sh[j] = hreg;
#pragma unroll
        for (int s = 0; s < 4; s++) x_sh[s][j] = xsrc[(size_t)s * XSTR + j];
    }
    __syncthreads();

    // xp(0), xp(1) into the xq ring; loaders stage x(4), x(5)
    xq_sh[0][j] = dot64(wih_, x_sh[0], bij);
    xq_sh[1][j] = dot64(wih_, x_sh[1], bij);
    float4 xa4 = make_float4(0.f, 0.f, 0.f, 0.f);
    float4 xb4 = xa4;
    if (loader) {
        xa4 = *(const float4*)&xsrc[(size_t)4 * XSTR + lj * 4];
        xb4 = *(const float4*)&xsrc[(size_t)5 * XSTR + lj * 4];
    }
    float* outp = out + (size_t)b * Tn * (Gn * Hn) + g * Hn + j;  // gates only
    __syncthreads();

#define STEP(T_, XREG_)                                                       \
    {                                                                         \
        /* phase A (critical): recurrent dot only; loaders refill x ring */   \
        float ghv = dot64(whh_, h_sh, bhj);                                   \
        gh_sh[j] = ghv;                                                       \
        if (loader) {                                                         \
            *(float4*)&x_sh[((T_) + 4) & 3][lj * 4] = XREG_;                  \
        }                                                                     \
        __syncthreads();                                                      \
        /* phase B: gates; xp(t+2) dot fills the MUFU bubbles; x LDG */       \
        if (gate) {                                                           \
            const float* xq = xq_sh[(T_) & 3];                                \
            float rr = fsig(xq[j]      + gh_sh[j]);                           \
            float zz = fsig(xq[64 + j] + gh_sh[64 + j]);                      \
            float aa = xq[128 + j] + rr * gh_sh[128 + j];                     \
            float nn = __fmaf_rn(2.f, fsig(2.f * aa), -1.f);                  \
            float hn = nn + zz * (hreg - nn);                                 \
            hreg = hn;                                                        \
            h_sh[j] = hn;                                                     \
            __stcs(&outp[(size_t)(T_) * (Gn * Hn)], hn);                      \
        }                                                                     \
        if ((T_) + 2 < Tn) {                                                  \
            int sl = ((T_) + 2) & 3;                                          \
            xq_sh[sl][j] = dot64(wih_, x_sh[sl], bij);                        \
        }                                                                     \
        if (loader) {                                                         \
            size_t tl = (size_t)min((T_) + 6, Tn - 1);                        \
            XREG_ = *(const float4*)&xsrc[tl * XSTR + lj * 4];                \
        }                                                                     \
        __syncthreads();                                                      \
    }

    for (int t = 0; t < Tn; t += 2) {
        STEP(t, xa4);
        STEP(t + 1, xb4);
    }
#undef STEP

    if (gate) {
        out[(size_t)Bn * Tn * (Gn * Hn) + ((size_t)g * Bn + b) * Hn + j] = hreg;
    }
}

// ---------------------------------------------------------------------------
extern "C" void kernel_launch(void* const* d_in, const int* in_sizes, int n_in,
                              void* d_out, int out_size)
{
    const float* x   = (const float*)d_in[0];
    const float* h0  = (const float*)d_in[1];
    const float* Wih = (const float*)d_in[2];
    const float* Whh = (const float*)d_in[3];
    const float* bih = (const float*)d_in[4];
    const float* bhh = (const float*)d_in[5];
    float* out = (float*)d_out;

    gru_fused_kernel<<<Bn * Gn, 192>>>(x, h0, Wih, Whh, bih, bhh, out);
}

// round 11
// speedup vs baseline: 1.1540x; 1.1271x over previous
#include <cuda_runtime.h>
#include <math.h>
#include <stdint.h>

#define Gn 8
#define Hn 64
#define In 64
#define Bn 32
#define Tn 1000
#define XSTR (Gn * In)   // 512 floats per (b,t)

// Scratch: xp[(bg*T + t)*192 + j], bg = b*G+g — written and read by block bg
__device__ float g_xp[(size_t)Bn * Gn * Tn * 192];

// ---------------- packed f32x2 helpers (sm_103a) ----------------
__device__ __forceinline__ uint64_t ffma2(uint64_t a, uint64_t b, uint64_t c) {
    uint64_t d;
    asm("fma.rn.f32x2 %0, %1, %2, %3;" : "=l"(d) : "l"(a), "l"(b), "l"(c));
    return d;
}
__device__ __forceinline__ uint64_t fadd2(uint64_t a, uint64_t b) {
    uint64_t d;
    asm("add.rn.f32x2 %0, %1, %2;" : "=l"(d) : "l"(a), "l"(b));
    return d;
}
__device__ __forceinline__ uint64_t pack2(float lo, float hi) {
    uint64_t d;
    asm("mov.b64 %0, {%1, %2};" : "=l"(d) : "f"(lo), "f"(hi));
    return d;
}
__device__ __forceinline__ float2 unpack2(uint64_t v) {
    float lo, hi;
    asm("mov.b64 {%0, %1}, %2;" : "=f"(lo), "=f"(hi) : "l"(v));
    return make_float2(lo, hi);
}
__device__ __forceinline__ float fsig(float x) {
    return __fdividef(1.f, 1.f + __expf(-x));
}

// 64-wide dot: w = 16 ulonglong2 (64 floats), v = 64 floats in smem (16B aligned)
__device__ __forceinline__ float dot64(const ulonglong2* w, const float* v, float seed) {
    const ulonglong2* v2 = (const ulonglong2*)v;
    uint64_t a0 = pack2(seed, 0.f), a1 = 0ull, a2 = 0ull, a3 = 0ull;
#pragma unroll
    for (int q = 0; q < 16; q += 2) {
        ulonglong2 va = v2[q];
        ulonglong2 vb = v2[q + 1];
        a0 = ffma2(w[q].x,     va.x, a0);
        a1 = ffma2(w[q].y,     va.y, a1);
        a2 = ffma2(w[q + 1].x, vb.x, a2);
        a3 = ffma2(w[q + 1].y, vb.y, a3);
    }
    float2 f = unpack2(fadd2(fadd2(a0, a1), fadd2(a2, a3)));
    return f.x + f.y;
}

// ---------------------------------------------------------------------------
// One block per (b,g), 192 threads, 2 blocks/SM.
// Phase 1: block-local xproj -> g_xp (no per-step barriers, dbl-buffered tiles)
// Phase 2: R2 scan (measured 478us) reading g_xp.
// ---------------------------------------------------------------------------
__global__ void __launch_bounds__(192, 2) gru_kernel(
    const float* __restrict__ x,
    const float* __restrict__ h0,
    const float* __restrict__ Wih,
    const float* __restrict__ Whh,
    const float* __restrict__ bih,
    const float* __restrict__ bhh,
    float* __restrict__ out)
{
    const int bg = blockIdx.x;
    const int b  = bg >> 3;
    const int g  = bg & 7;
    const int j  = threadIdx.x;

    __shared__ __align__(16) float xt[2][8][64];   // x tiles (8 timesteps)
    __shared__ __align__(16) float h_sh[64];
    __shared__ __align__(16) float gh_sh[192];
    __shared__ __align__(16) float xq_sh[192];

    const float* xsrc = x + ((size_t)b * Tn) * XSTR + g * In;
    float* xp = g_xp + (size_t)bg * Tn * 192;

    // ================= Phase 1: xp = Wih @ x + bih =================
    {
        ulonglong2 wih_[16];
        const ulonglong2* p = (const ulonglong2*)&Wih[((size_t)g * 192 + j) * In];
#pragma unroll
        for (int q = 0; q < 16; q++) wih_[q] = p[q];
        const float bij = bih[g * 192 + j];

        const bool ldr = (j < 128);
        const int  tt  = j >> 4;    // 0..7 (timestep within tile)
        const int  qq  = j & 15;    // 0..15 (float4 within row)

        if (ldr) {
            float4 v0 = *(const float4*)&xsrc[(size_t)tt * XSTR + qq * 4];
            *(float4*)&xt[0][tt][qq * 4] = v0;
        }
        __syncthreads();

        for (int tile = 0; tile < Tn / 8; tile++) {
            const int buf = tile & 1;
            float4 vnext = make_float4(0.f, 0.f, 0.f, 0.f);
            const bool more = (tile + 1 < Tn / 8);
            if (more && ldr) {
                vnext = *(const float4*)&xsrc[(size_t)((tile + 1) * 8 + tt) * XSTR + qq * 4];
            }
            float r[8];
#pragma unroll
            for (int u = 0; u < 8; u++) r[u] = dot64(wih_, xt[buf][u], bij);
#pragma unroll
            for (int u = 0; u < 8; u++) xp[(size_t)(tile * 8 + u) * 192 + j] = r[u];
            if (more && ldr) {
                *(float4*)&xt[buf ^ 1][tt][qq * 4] = vnext;
            }
            __syncthreads();
        }
    }

    // ================= Phase 2: R2 scan =================
    // Whh row j -> registers (loaded after phase 1 to relieve pressure)
    ulonglong2 w[16];
    {
        const ulonglong2* wrow = (const ulonglong2*)&Whh[((size_t)g * 192 + j) * Hn];
#pragma unroll
        for (int q = 0; q < 16; q++) w[q] = wrow[q];
    }
    const float bj = bhh[g * 192 + j];

    if (j < 64) h_sh[j] = h0[((size_t)g * Bn + b) * Hn + j];

    const float* xp_col = xp + j;
    float* out_row = out + (size_t)b * Tn * (Gn * Hn) + g * Hn;

#define STEP(T_, XV_)                                                         \
    {                                                                         \
        __syncthreads();   /* h_sh ready; also phase1->phase2 visibility */   \
        uint64_t A0 = pack2(bj, 0.f), A1 = 0ull, A2 = 0ull, A3 = 0ull;        \
        const ulonglong2* h2 = (const ulonglong2*)h_sh;                       \
        _Pragma("unroll")                                                     \
        for (int q = 0; q < 16; q += 2) {                                     \
            ulonglong2 ha = h2[q];                                            \
            ulonglong2 hb = h2[q + 1];                                        \
            A0 = ffma2(w[q].x,     ha.x, A0);                                 \
            A1 = ffma2(w[q].y,     ha.y, A1);                                 \
            A2 = ffma2(w[q + 1].x, hb.x, A2);                                 \
            A3 = ffma2(w[q + 1].y, hb.y, A3);                                 \
        }                                                                     \
        float2 s_ = unpack2(fadd2(fadd2(A0, A1), fadd2(A2, A3)));             \
        gh_sh[j] = s_.x + s_.y;                                               \
        xq_sh[j] = XV_;                                                       \
        __syncthreads();                                                      \
        if (j < 64) {                                                         \
            float hprev = h_sh[j];                                            \
            float rr = fsig(xq_sh[j]      + gh_sh[j]);                        \
            float zz = fsig(xq_sh[64 + j] + gh_sh[64 + j]);                   \
            float aa = xq_sh[128 + j] + rr * gh_sh[128 + j];                  \
            float nn = __fmaf_rn(2.f, fsig(2.f * aa), -1.f);                  \
            float hn = nn + zz * (hprev - nn);                                \
            h_sh[j] = hn;                                                     \
            __stcs(&out_row[(size_t)(T_) * (Gn * Hn) + j], hn);               \
        }                                                                     \
    }

    // 4-deep register prefetch ring (R2)
    float p0 = xp_col[0];
    float p1 = xp_col[192];
    float p2 = xp_col[2 * 192];
    float p3 = xp_col[3 * 192];

    for (int t = 0; t < Tn; t += 4) {
        STEP(t, p0);
        { int tp = min(t + 4, Tn - 1); p0 = xp_col[(size_t)tp * 192]; }
        STEP(t + 1, p1);
        { int tp = min(t + 5, Tn - 1); p1 = xp_col[(size_t)tp * 192]; }
        STEP(t + 2, p2);
        { int tp = min(t + 6, Tn - 1); p2 = xp_col[(size_t)tp * 192]; }
        STEP(t + 3, p3);
        { int tp = min(t + 7, Tn - 1); p3 = xp_col[(size_t)tp * 192]; }
    }
#undef STEP

    __syncthreads();
    if (j < 64) {
        out[(size_t)Bn * Tn * (Gn * Hn) + ((size_t)g * Bn + b) * Hn + j] = h_sh[j];
    }
}

// ---------------------------------------------------------------------------
extern "C" void kernel_launch(void* const* d_in, const int* in_sizes, int n_in,
                              void* d_out, int out_size)
{
    const float* x   = (const float*)d_in[0];
    const float* h0  = (const float*)d_in[1];
    const float* Wih = (const float*)d_in[2];
    const float* Whh = (const float*)d_in[3];
    const float* bih = (const float*)d_in[4];
    const float* bhh = (const float*)d_in[5];
    float* out = (float*)d_out;

    gru_kernel<<<Bn * Gn, 192>>>(x, h0, Wih, Whh, bih, bhh, out);
}